// round 1
// baseline (speedup 1.0000x reference)
#include <cuda_runtime.h>
#include <math.h>

#define NROWS 32768
#define DIN   960
#define DH    1920

// ---- scratch (static device memory; no allocations anywhere) ----
__device__ float g_xp[NROWS * DIN];    // x in planar (component-major) layout
__device__ float g_h1[NROWS * DH];     // hidden 1 (planar)
__device__ float g_h2[NROWS * DH];     // hidden 2 (planar)
__device__ float g_outp[NROWS * DIN];  // pre-BN output (planar)
__device__ float g_sum0[256];          // scalar-channel sums
__device__ float g_ssq[448];           // sumsq: [0,256) scalars, [256,384) l1, [384,448) l2

// Planar layout for dim-960 (IRR_IN/IRR_OUT):
//   l0: [0,256)        channel c -> c
//   l1: [256,640)      plane i (0..2) at 256 + i*128, channel u -> +u
//   l2: [640,960)      plane i (0..4) at 640 + i*64,  channel u -> +u
// Planar layout for dim-1920 (IRR_H):
//   l0: [0,512); l1: 512 + i*256; l2: 1280 + i*128

// ---------------- interleaved -> planar transpose of x ----------------
__global__ void to_planar_kernel(const float* __restrict__ x) {
    int idx = blockIdx.x * 256 + threadIdx.x;
    if (idx >= NROWS * DIN) return;
    int n = idx / DIN, j = idx - n * DIN;
    int src;
    if (j < 256) {
        src = j;
    } else if (j < 640) {
        int p = j - 256;               // i = p>>7, u = p&127
        src = 256 + (p & 127) * 3 + (p >> 7);
    } else {
        int p = j - 640;               // i = p>>6, u = p&63
        src = 640 + (p & 63) * 5 + (p >> 6);
    }
    g_xp[idx] = x[n * DIN + src];
}

// ---------------- fp32 GEMM: C[M,Nout](tile) = alpha * A[M,K] @ B[K,Nout] (+C) ----
// Tiles: BM=128, BN=64, BK=16, 256 threads, 8x4 per thread.
// Requires: M%128==0, Nout%64==0, K%16==0 (all true for this problem).
__global__ __launch_bounds__(256) void sgemm_kernel(
    const float* __restrict__ A, int lda,
    const float* __restrict__ B, int ldb,
    float* __restrict__ C, int ldc,
    int K, float alpha, int accumulate)
{
    __shared__ float As[16][128];
    __shared__ float Bs[16][64];

    const int tid  = threadIdx.x;
    const int tx   = tid & 15;        // 0..15 -> 4 cols each
    const int ty   = tid >> 4;        // 0..15 -> 8 rows each
    const int row0 = blockIdx.y << 7;
    const int n0   = blockIdx.x << 6;

    const int am = tid >> 1;          // 0..127 row within A tile
    const int ak = (tid & 1) << 3;    // 0 or 8
    const int bk = tid >> 4;          // 0..15
    const int bn = (tid & 15) << 2;   // 0..60

    const float* Ag = A + (row0 + am) * lda + ak;
    const float* Bg = B + bk * ldb + n0 + bn;

    float acc[8][4];
    #pragma unroll
    for (int i = 0; i < 8; i++)
        #pragma unroll
        for (int j = 0; j < 4; j++) acc[i][j] = 0.0f;

    for (int k0 = 0; k0 < K; k0 += 16) {
        float4 a0 = *(const float4*)(Ag + k0);
        float4 a1 = *(const float4*)(Ag + k0 + 4);
        float4 bv = *(const float4*)(Bg + k0 * ldb);

        As[ak + 0][am] = a0.x; As[ak + 1][am] = a0.y;
        As[ak + 2][am] = a0.z; As[ak + 3][am] = a0.w;
        As[ak + 4][am] = a1.x; As[ak + 5][am] = a1.y;
        As[ak + 6][am] = a1.z; As[ak + 7][am] = a1.w;
        *(float4*)&Bs[bk][bn] = bv;
        __syncthreads();

        #pragma unroll
        for (int k = 0; k < 16; k++) {
            float4 b4  = *(float4*)&Bs[k][tx << 2];
            float4 a04 = *(float4*)&As[k][ty << 3];
            float4 a14 = *(float4*)&As[k][(ty << 3) + 4];
            float a[8] = {a04.x, a04.y, a04.z, a04.w, a14.x, a14.y, a14.z, a14.w};
            float b[4] = {b4.x, b4.y, b4.z, b4.w};
            #pragma unroll
            for (int i = 0; i < 8; i++)
                #pragma unroll
                for (int j = 0; j < 4; j++)
                    acc[i][j] = fmaf(a[i], b[j], acc[i][j]);
        }
        __syncthreads();
    }

    #pragma unroll
    for (int i = 0; i < 8; i++) {
        float* Cp = C + (row0 + (ty << 3) + i) * ldc + n0 + (tx << 2);
        float4 v;
        v.x = acc[i][0] * alpha; v.y = acc[i][1] * alpha;
        v.z = acc[i][2] * alpha; v.w = acc[i][3] * alpha;
        if (accumulate) {
            float4 c = *(const float4*)Cp;
            v.x += c.x; v.y += c.y; v.z += c.z; v.w += c.w;
        }
        *(float4*)Cp = v;
    }
}

// ---------------- NormActivation (in place, planar) ----------------
// f *= sigmoid(|f|)/|f|, |f| = sqrt(sum_i f_i^2 + 1e-8)
template <int L>
__global__ void normact_kernel(float* __restrict__ H, int o, int m) {
    int idx = blockIdx.x * 256 + threadIdx.x;
    if (idx >= NROWS * m) return;
    int n = idx / m, v = idx - n * m;
    float* p = H + n * DH + o + v;
    float f[L];
    float s2 = 1e-8f;
    #pragma unroll
    for (int i = 0; i < L; i++) { f[i] = p[i * m]; s2 += f[i] * f[i]; }
    float nn = sqrtf(s2);
    float sg = 1.0f / (1.0f + expf(-nn));
    float sc = sg / nn;
    #pragma unroll
    for (int i = 0; i < L; i++) p[i * m] = f[i] * sc;
}

// ---------------- BatchNorm ----------------
__global__ void bn_zero_kernel() {
    int t = threadIdx.x;
    if (t < 256) g_sum0[t] = 0.0f;
    if (t < 448) g_ssq[t]  = 0.0f;
}

__global__ void bn_reduce_kernel() {
    const int tid = threadIdx.x;           // 256
    const int r0  = blockIdx.x * 512;      // 64 blocks * 512 rows
    float s[4] = {0, 0, 0, 0}, q[4] = {0, 0, 0, 0};
    for (int r = 0; r < 512; r++) {
        const float* row = g_outp + (r0 + r) * DIN;
        #pragma unroll
        for (int k = 0; k < 4; k++) {
            int j = tid + (k << 8);
            if (j < DIN) {
                float v = row[j];
                s[k] += v;
                q[k] += v * v;
            }
        }
    }
    #pragma unroll
    for (int k = 0; k < 4; k++) {
        int j = tid + (k << 8);
        if (j >= DIN) continue;
        if (j < 256) {
            atomicAdd(&g_sum0[j], s[k]);
            atomicAdd(&g_ssq[j], q[k]);
        } else if (j < 640) {
            int v = (j - 256) & 127;
            atomicAdd(&g_ssq[256 + v], q[k]);
        } else {
            int v = (j - 640) & 63;
            atomicAdd(&g_ssq[384 + v], q[k]);
        }
    }
}

// reads planar g_outp, writes interleaved output with BN applied
__global__ void bn_apply_kernel(const float* __restrict__ bnw,
                                const float* __restrict__ bnb,
                                float* __restrict__ out) {
    int idx = blockIdx.x * 256 + threadIdx.x;
    if (idx >= NROWS * DIN) return;
    int n = idx / DIN, jo = idx - n * DIN;
    const float invN = 1.0f / (float)NROWS;
    float g;
    if (jo < 256) {
        float f   = g_outp[n * DIN + jo];
        float mu  = g_sum0[jo] * invN;
        float var = g_ssq[jo] * invN - mu * mu;
        g = (f - mu) * bnw[jo] * rsqrtf(var + 1e-5f) + bnb[jo];
    } else if (jo < 640) {
        int p = jo - 256, v = p / 3, i = p - v * 3;
        float f  = g_outp[n * DIN + 256 + (i << 7) + v];
        float n2 = g_ssq[256 + v] * (invN * (1.0f / 3.0f));
        g = f * bnw[256 + v] * rsqrtf(n2 + 1e-5f);
    } else {
        int p = jo - 640, v = p / 5, i = p - v * 5;
        float f  = g_outp[n * DIN + 640 + (i << 6) + v];
        float n2 = g_ssq[384 + v] * (invN * (1.0f / 5.0f));
        g = f * bnw[384 + v] * rsqrtf(n2 + 1e-5f);
    }
    out[idx] = g;
}

// ---------------- launch ----------------
extern "C" void kernel_launch(void* const* d_in, const int* in_sizes, int n_in,
                              void* d_out, int out_size) {
    const float* x   = (const float*)d_in[0];
    const float* w1  = (const float*)d_in[1];
    const float* w2  = (const float*)d_in[2];
    const float* w3  = (const float*)d_in[3];
    const float* wb  = (const float*)d_in[4];
    const float* bnw = (const float*)d_in[5];
    const float* bnb = (const float*)d_in[6];
    float* out = (float*)d_out;

    float *xp, *h1, *h2, *op;
    cudaGetSymbolAddress((void**)&xp, g_xp);
    cudaGetSymbolAddress((void**)&h1, g_h1);
    cudaGetSymbolAddress((void**)&h2, g_h2);
    cudaGetSymbolAddress((void**)&op, g_outp);

    const float a256 = 0.0625f;             // 1/sqrt(256)
    const float a128 = 0.08838834764831845f; // 1/sqrt(128)
    const float a64  = 0.125f;              // 1/sqrt(64)
    const float a512 = 0.044194173824159216f; // 1/sqrt(512)

    auto gemm = [&](const float* A, int lda, const float* B, int ldb,
                    float* C, int ldc, int K, int Nout, float alpha, int acc) {
        dim3 grid(Nout / 64, NROWS / 128);
        sgemm_kernel<<<grid, 256>>>(A, lda, B, ldb, C, ldc, K, alpha, acc);
    };

    // 0) transpose x to planar
    to_planar_kernel<<<(NROWS * DIN) / 256, 256>>>(x);

    // 1) linear1: IRR_IN -> IRR_H
    gemm(xp, DIN, w1, 512, h1, DH, 256, 512, a256, 0);
    for (int i = 0; i < 3; i++)
        gemm(xp + 256 + i * 128, DIN, w1 + 131072, 256, h1 + 512 + i * 256, DH, 128, 256, a128, 0);
    for (int i = 0; i < 5; i++)
        gemm(xp + 640 + i * 64, DIN, w1 + 163840, 128, h1 + 1280 + i * 128, DH, 64, 128, a64, 0);

    // 2) norm-act on h1
    normact_kernel<1><<<(NROWS * 512) / 256, 256>>>(h1, 0, 512);
    normact_kernel<3><<<(NROWS * 256) / 256, 256>>>(h1, 512, 256);
    normact_kernel<5><<<(NROWS * 128) / 256, 256>>>(h1, 1280, 128);

    // 3) linear2: IRR_H -> IRR_H
    gemm(h1, DH, w2, 512, h2, DH, 512, 512, a512, 0);
    for (int i = 0; i < 3; i++)
        gemm(h1 + 512 + i * 256, DH, w2 + 262144, 256, h2 + 512 + i * 256, DH, 256, 256, a256, 0);
    for (int i = 0; i < 5; i++)
        gemm(h1 + 1280 + i * 128, DH, w2 + 327680, 128, h2 + 1280 + i * 128, DH, 128, 128, a128, 0);

    // 4) norm-act on h2
    normact_kernel<1><<<(NROWS * 512) / 256, 256>>>(h2, 0, 512);
    normact_kernel<3><<<(NROWS * 256) / 256, 256>>>(h2, 512, 256);
    normact_kernel<5><<<(NROWS * 128) / 256, 256>>>(h2, 1280, 128);

    // 5) linear3: IRR_H -> IRR_OUT (write)
    gemm(h2, DH, w3, 256, op, DIN, 512, 256, a512, 0);
    for (int i = 0; i < 3; i++)
        gemm(h2 + 512 + i * 256, DH, w3 + 131072, 128, op + 256 + i * 128, DIN, 256, 128, a256, 0);
    for (int i = 0; i < 5; i++)
        gemm(h2 + 1280 + i * 128, DH, w3 + 163840, 64, op + 640 + i * 64, DIN, 128, 64, a128, 0);

    // 6) skip: linear(x, wb) accumulated into op
    gemm(xp, DIN, wb, 256, op, DIN, 256, 256, a256, 1);
    for (int i = 0; i < 3; i++)
        gemm(xp + 256 + i * 128, DIN, wb + 65536, 128, op + 256 + i * 128, DIN, 128, 128, a128, 1);
    for (int i = 0; i < 5; i++)
        gemm(xp + 640 + i * 64, DIN, wb + 81920, 64, op + 640 + i * 64, DIN, 64, 64, a64, 1);

    // 7) batch norm -> interleaved output
    bn_zero_kernel<<<1, 512>>>();
    bn_reduce_kernel<<<64, 256>>>();
    bn_apply_kernel<<<(NROWS * DIN) / 256, 256>>>(bnw, bnb, out);
}

// round 5
// speedup vs baseline: 1.3635x; 1.3635x over previous
#include <cuda_runtime.h>
#include <math.h>
#include <stdint.h>

#define NROWS 32768
#define DIN   960
#define DH    1920

// ---------------- static device buffers (no allocations) ----------------
__device__ float g_xp [(size_t)NROWS * DIN];   // x planar fp32
__device__ float g_h1 [(size_t)NROWS * DH];
__device__ float g_h2 [(size_t)NROWS * DH];
__device__ float g_outp[(size_t)NROWS * DIN];
__device__ float g_sum0[256];
__device__ float g_ssq[448];
__device__ float g_wt1[172032];   // transposed [Nout,K] fp32, alpha folded
__device__ float g_wt2[344064];
__device__ float g_wt3[172032];
__device__ float g_wtb[86016];

// ---------------- helpers ----------------
__device__ __forceinline__ uint32_t s2u(const void* p) {
    uint32_t a;
    asm("{ .reg .u64 t; cvta.to.shared.u64 t, %1; cvt.u32.u64 %0, t; }"
        : "=r"(a) : "l"(p));
    return a;
}

__device__ __forceinline__ void cp16(uint32_t dst, const void* src) {
    asm volatile("cp.async.cg.shared.global [%0], [%1], 16;"
                 :: "r"(dst), "l"(src));
}

__device__ __forceinline__ uint32_t f2tf(float x) {
    uint32_t r;
    asm("cvt.rna.tf32.f32 %0, %1;" : "=r"(r) : "f"(x));
    return r;
}

__device__ __forceinline__ void mma_tf32(float* d, const uint32_t* a,
                                         uint32_t b0, uint32_t b1) {
    asm volatile(
        "mma.sync.aligned.m16n8k8.row.col.f32.tf32.tf32.f32 "
        "{%0,%1,%2,%3}, {%4,%5,%6,%7}, {%8,%9}, {%0,%1,%2,%3};"
        : "+f"(d[0]), "+f"(d[1]), "+f"(d[2]), "+f"(d[3])
        : "r"(a[0]), "r"(a[1]), "r"(a[2]), "r"(a[3]), "r"(b0), "r"(b1));
}

// ---------------- 3xTF32 GEMM ----------------
// C[M, Nout](+)= A[M,K] @ B[Nout,K]^T (fp32 in, fp32 out, 3xTF32 products)
// blockIdx.z batches independent blocks with A/C column strides.
// BM=128, BN=128 or 64, BK=16, 256 threads, 2-stage cp.async pipeline.
// smem pitch = 20 floats (80B): 16B-aligned for cp.async, conflict-free frags.
template <int BN>
__global__ __launch_bounds__(256, 2) void gemm_tf32(
    const float* __restrict__ A, int lda, size_t sAz,
    const float* __restrict__ B, int ldb,
    float* __restrict__ C, int ldc, size_t sCz,
    int nc, int accumulate)
{
    constexpr int WN = (BN == 128) ? 4 : 2;   // warps along N
    constexpr int MT = (BN == 128) ? 4 : 2;   // m16-tiles per warp
    __shared__ __align__(16) float sA[2][128 * 20];
    __shared__ __align__(16) float sB[2][BN * 20];

    A += (size_t)blockIdx.z * sAz;
    C += (size_t)blockIdx.z * sCz;

    const int tid = threadIdx.x, wid = tid >> 5, lane = tid & 31;
    const int g = lane >> 2, t = lane & 3;
    const int wm = wid / WN, wn = wid % WN;
    const int row0 = blockIdx.y << 7;
    const int n0   = blockIdx.x * BN;

    float acc[MT][4][4];
    #pragma unroll
    for (int i = 0; i < MT; i++)
        #pragma unroll
        for (int j = 0; j < 4; j++)
            #pragma unroll
            for (int k = 0; k < 4; k++) acc[i][j][k] = 0.0f;

    auto issue = [&](int c, int s) {
        const float* Asrc = A + (size_t)row0 * lda + c * 16;
        const float* Bsrc = B + (size_t)n0 * ldb + c * 16;
        uint32_t da = s2u(&sA[s][0]);
        #pragma unroll
        for (int i = tid; i < 512; i += 256) {
            int r = i >> 2, u = i & 3;
            cp16(da + r * 80 + u * 16, Asrc + (size_t)r * lda + u * 4);
        }
        uint32_t db = s2u(&sB[s][0]);
        #pragma unroll
        for (int i = tid; i < BN * 4; i += 256) {
            int r = i >> 2, u = i & 3;
            cp16(db + r * 80 + u * 16, Bsrc + (size_t)r * ldb + u * 4);
        }
        asm volatile("cp.async.commit_group;");
    };

    issue(0, 0);
    if (nc > 1) issue(1, 1);

    for (int cc = 0; cc < nc; cc++) {
        if (cc + 1 < nc)
            asm volatile("cp.async.wait_group 1;");
        else
            asm volatile("cp.async.wait_group 0;");
        __syncthreads();

        const int s = cc & 1;
        const float* a = &sA[s][0];
        const float* b = &sB[s][0];

        #pragma unroll
        for (int ks = 0; ks < 2; ks++) {
            const int kb = ks * 8;
            // B fragments: hi/lo tf32
            uint32_t bhi[4][2], blo[4][2];
            #pragma unroll
            for (int nt = 0; nt < 4; nt++) {
                int nr = wn * 32 + nt * 8 + g;
                float f0 = b[nr * 20 + kb + t];
                float f1 = b[nr * 20 + kb + 4 + t];
                bhi[nt][0] = f2tf(f0);
                blo[nt][0] = f2tf(f0 - __uint_as_float(bhi[nt][0]));
                bhi[nt][1] = f2tf(f1);
                blo[nt][1] = f2tf(f1 - __uint_as_float(bhi[nt][1]));
            }
            #pragma unroll
            for (int mt = 0; mt < MT; mt++) {
                int r0 = wm * (MT * 16) + mt * 16 + g;
                float a0 = a[r0 * 20 + kb + t];
                float a1 = a[(r0 + 8) * 20 + kb + t];
                float a2 = a[r0 * 20 + kb + 4 + t];
                float a3 = a[(r0 + 8) * 20 + kb + 4 + t];
                uint32_t ahi[4], alo[4];
                ahi[0] = f2tf(a0); alo[0] = f2tf(a0 - __uint_as_float(ahi[0]));
                ahi[1] = f2tf(a1); alo[1] = f2tf(a1 - __uint_as_float(ahi[1]));
                ahi[2] = f2tf(a2); alo[2] = f2tf(a2 - __uint_as_float(ahi[2]));
                ahi[3] = f2tf(a3); alo[3] = f2tf(a3 - __uint_as_float(ahi[3]));
                #pragma unroll
                for (int nt = 0; nt < 4; nt++) {
                    mma_tf32(acc[mt][nt], ahi, bhi[nt][0], bhi[nt][1]);
                    mma_tf32(acc[mt][nt], ahi, blo[nt][0], blo[nt][1]);
                    mma_tf32(acc[mt][nt], alo, bhi[nt][0], bhi[nt][1]);
                }
            }
        }
        __syncthreads();
        if (cc + 2 < nc) issue(cc + 2, s);
    }

    // epilogue: register -> global (float2), optional accumulate
    const int tig = lane & 3;
    #pragma unroll
    for (int mt = 0; mt < MT; mt++) {
        int r = row0 + wm * (MT * 16) + mt * 16 + g;
        #pragma unroll
        for (int nt = 0; nt < 4; nt++) {
            int cI = n0 + wn * 32 + nt * 8 + tig * 2;
            float* p0 = C + (size_t)r * ldc + cI;
            float* p1 = p0 + (size_t)8 * ldc;
            float2 v0 = make_float2(acc[mt][nt][0], acc[mt][nt][1]);
            float2 v1 = make_float2(acc[mt][nt][2], acc[mt][nt][3]);
            if (accumulate) {
                float2 c0 = *(float2*)p0, c1 = *(float2*)p1;
                v0.x += c0.x; v0.y += c0.y;
                v1.x += c1.x; v1.y += c1.y;
            }
            *(float2*)p0 = v0;
            *(float2*)p1 = v1;
        }
    }
}

// ---------------- weight transpose: fp32 [K,Nout] -> fp32 [Nout,K], alpha folded
__global__ void conv_w_kernel(const float* __restrict__ W, float* __restrict__ Wt,
                              int K, int Nout, float alpha) {
    int idx = blockIdx.x * 256 + threadIdx.x;
    if (idx >= K * Nout) return;
    int u = idx / Nout, v = idx - u * Nout;
    Wt[(size_t)v * K + u] = W[idx] * alpha;
}

// ---------------- x interleaved -> planar fp32 ----------------
__global__ void to_planar_kernel(const float* __restrict__ x) {
    int idx = blockIdx.x * 256 + threadIdx.x;
    if (idx >= NROWS * DIN) return;
    int n = idx / DIN, j = idx - n * DIN;
    int src;
    if (j < 256) {
        src = j;
    } else if (j < 640) {
        int p = j - 256;
        src = 256 + (p & 127) * 3 + (p >> 7);
    } else {
        int p = j - 640;
        src = 640 + (p & 63) * 5 + (p >> 6);
    }
    g_xp[idx] = x[(size_t)n * DIN + src];
}

// ---------------- NormActivation (in place, planar fp32) ----------------
template <int L>
__global__ void normact_kernel(float* __restrict__ H, int o, int m) {
    int idx = blockIdx.x * 256 + threadIdx.x;
    if (idx >= NROWS * m) return;
    int n = idx / m, v = idx - n * m;
    float* p = H + (size_t)n * DH + o + v;
    float f[L];
    float s2 = 1e-8f;
    #pragma unroll
    for (int i = 0; i < L; i++) { f[i] = p[(size_t)i * m]; s2 += f[i] * f[i]; }
    float nn = sqrtf(s2);
    float sg = 1.0f / (1.0f + expf(-nn));
    float sc = sg / nn;
    #pragma unroll
    for (int i = 0; i < L; i++) p[(size_t)i * m] = f[i] * sc;
}

// ---------------- BatchNorm ----------------
__global__ void bn_zero_kernel() {
    int t = threadIdx.x;
    if (t < 256) g_sum0[t] = 0.0f;
    if (t < 448) g_ssq[t]  = 0.0f;
}

__global__ void bn_reduce_kernel() {
    const int tid = threadIdx.x;
    const int r0  = blockIdx.x * 512;
    float s[4] = {0, 0, 0, 0}, q[4] = {0, 0, 0, 0};
    for (int r = 0; r < 512; r++) {
        const float* row = g_outp + (size_t)(r0 + r) * DIN;
        #pragma unroll
        for (int k = 0; k < 4; k++) {
            int j = tid + (k << 8);
            if (j < DIN) {
                float v = row[j];
                s[k] += v;
                q[k] += v * v;
            }
        }
    }
    #pragma unroll
    for (int k = 0; k < 4; k++) {
        int j = tid + (k << 8);
        if (j >= DIN) continue;
        if (j < 256) {
            atomicAdd(&g_sum0[j], s[k]);
            atomicAdd(&g_ssq[j], q[k]);
        } else if (j < 640) {
            atomicAdd(&g_ssq[256 + ((j - 256) & 127)], q[k]);
        } else {
            atomicAdd(&g_ssq[384 + ((j - 640) & 63)], q[k]);
        }
    }
}

__global__ void bn_apply_kernel(const float* __restrict__ bnw,
                                const float* __restrict__ bnb,
                                float* __restrict__ out) {
    int idx = blockIdx.x * 256 + threadIdx.x;
    if (idx >= NROWS * DIN) return;
    int n = idx / DIN, jo = idx - n * DIN;
    const float invN = 1.0f / (float)NROWS;
    float g;
    if (jo < 256) {
        float f   = g_outp[(size_t)n * DIN + jo];
        float mu  = g_sum0[jo] * invN;
        float var = g_ssq[jo] * invN - mu * mu;
        g = (f - mu) * bnw[jo] * rsqrtf(var + 1e-5f) + bnb[jo];
    } else if (jo < 640) {
        int p = jo - 256, v = p / 3, i = p - v * 3;
        float f  = g_outp[(size_t)n * DIN + 256 + (i << 7) + v];
        float n2 = g_ssq[256 + v] * (invN * (1.0f / 3.0f));
        g = f * bnw[256 + v] * rsqrtf(n2 + 1e-5f);
    } else {
        int p = jo - 640, v = p / 5, i = p - v * 5;
        float f  = g_outp[(size_t)n * DIN + 640 + (i << 6) + v];
        float n2 = g_ssq[384 + v] * (invN * (1.0f / 5.0f));
        g = f * bnw[384 + v] * rsqrtf(n2 + 1e-5f);
    }
    out[idx] = g;
}

// ---------------- launch ----------------
extern "C" void kernel_launch(void* const* d_in, const int* in_sizes, int n_in,
                              void* d_out, int out_size) {
    const float* x   = (const float*)d_in[0];
    const float* w1  = (const float*)d_in[1];
    const float* w2  = (const float*)d_in[2];
    const float* w3  = (const float*)d_in[3];
    const float* wb  = (const float*)d_in[4];
    const float* bnw = (const float*)d_in[5];
    const float* bnb = (const float*)d_in[6];
    float* out = (float*)d_out;

    float *xp, *h1, *h2, *op, *wt1, *wt2, *wt3, *wtb;
    cudaGetSymbolAddress((void**)&xp,  g_xp);
    cudaGetSymbolAddress((void**)&h1,  g_h1);
    cudaGetSymbolAddress((void**)&h2,  g_h2);
    cudaGetSymbolAddress((void**)&op,  g_outp);
    cudaGetSymbolAddress((void**)&wt1, g_wt1);
    cudaGetSymbolAddress((void**)&wt2, g_wt2);
    cudaGetSymbolAddress((void**)&wt3, g_wt3);
    cudaGetSymbolAddress((void**)&wtb, g_wtb);

    auto cw = [&](const float* W, float* Wt, int K, int Nout) {
        int n = K * Nout;
        conv_w_kernel<<<(n + 255) / 256, 256>>>(W, Wt, K, Nout, 1.0f / sqrtf((float)K));
    };
    cw(w1,          wt1,          256, 512);
    cw(w1 + 131072, wt1 + 131072, 128, 256);
    cw(w1 + 163840, wt1 + 163840,  64, 128);
    cw(w2,          wt2,          512, 512);
    cw(w2 + 262144, wt2 + 262144, 256, 256);
    cw(w2 + 327680, wt2 + 327680, 128, 128);
    cw(w3,          wt3,          512, 256);
    cw(w3 + 131072, wt3 + 131072, 256, 128);
    cw(w3 + 163840, wt3 + 163840, 128,  64);
    cw(wb,          wtb,          256, 256);
    cw(wb + 65536,  wtb + 65536,  128, 128);
    cw(wb + 81920,  wtb + 81920,   64,  64);

    to_planar_kernel<<<(NROWS * DIN) / 256, 256>>>(x);

    auto gemm = [&](const float* A, int lda, size_t sAz,
                    const float* B,
                    float* Cp, int ldc, size_t sCz,
                    int K, int Nout, int nz, int acc) {
        if (Nout >= 128) {
            dim3 grid(Nout / 128, NROWS / 128, nz);
            gemm_tf32<128><<<grid, 256>>>(A, lda, sAz, B, K, Cp, ldc, sCz, K / 16, acc);
        } else {
            dim3 grid(Nout / 64, NROWS / 128, nz);
            gemm_tf32<64><<<grid, 256>>>(A, lda, sAz, B, K, Cp, ldc, sCz, K / 16, acc);
        }
    };

    // layer 1: xp -> h1
    gemm(xp,        DIN, 0,   wt1,          h1,        DH, 0,   256, 512, 1, 0);
    gemm(xp + 256,  DIN, 128, wt1 + 131072, h1 + 512,  DH, 256, 128, 256, 3, 0);
    gemm(xp + 640,  DIN, 64,  wt1 + 163840, h1 + 1280, DH, 128,  64, 128, 5, 0);

    normact_kernel<1><<<(NROWS * 512) / 256, 256>>>(h1, 0, 512);
    normact_kernel<3><<<(NROWS * 256) / 256, 256>>>(h1, 512, 256);
    normact_kernel<5><<<(NROWS * 128) / 256, 256>>>(h1, 1280, 128);

    // layer 2: h1 -> h2
    gemm(h1,        DH, 0,    wt2,          h2,        DH, 0,   512, 512, 1, 0);
    gemm(h1 + 512,  DH, 256,  wt2 + 262144, h2 + 512,  DH, 256, 256, 256, 3, 0);
    gemm(h1 + 1280, DH, 128,  wt2 + 327680, h2 + 1280, DH, 128, 128, 128, 5, 0);

    normact_kernel<1><<<(NROWS * 512) / 256, 256>>>(h2, 0, 512);
    normact_kernel<3><<<(NROWS * 256) / 256, 256>>>(h2, 512, 256);
    normact_kernel<5><<<(NROWS * 128) / 256, 256>>>(h2, 1280, 128);

    // layer 3: h2 -> op (write)
    gemm(h2,        DH, 0,    wt3,          op,        DIN, 0,   512, 256, 1, 0);
    gemm(h2 + 512,  DH, 256,  wt3 + 131072, op + 256,  DIN, 128, 256, 128, 3, 0);
    gemm(h2 + 1280, DH, 128,  wt3 + 163840, op + 640,  DIN, 64,  128,  64, 5, 0);

    // skip: xp -> op (accumulate)
    gemm(xp,        DIN, 0,   wtb,          op,        DIN, 0,   256, 256, 1, 1);
    gemm(xp + 256,  DIN, 128, wtb + 65536,  op + 256,  DIN, 128, 128, 128, 3, 1);
    gemm(xp + 640,  DIN, 64,  wtb + 81920,  op + 640,  DIN, 64,   64,  64, 5, 1);

    // batch norm -> interleaved fp32 output
    bn_zero_kernel<<<1, 512>>>();
    bn_reduce_kernel<<<64, 256>>>();
    bn_apply_kernel<<<(NROWS * DIN) / 256, 256>>>(bnw, bnb, out);
}

// round 7
// speedup vs baseline: 1.5356x; 1.1262x over previous
#include <cuda_runtime.h>
#include <math.h>
#include <stdint.h>

#define NROWS 32768
#define DIN   960
#define DH    1920

// ---------------- static device buffers (no allocations) ----------------
__device__ float g_xp [(size_t)NROWS * DIN];   // x planar fp32
__device__ float g_h1 [(size_t)NROWS * DH];
__device__ float g_h2 [(size_t)NROWS * DH];
__device__ float g_outp[(size_t)NROWS * DIN];
__device__ float g_sum0[256];
__device__ float g_ssq[448];
__device__ float g_wt1[172032];   // transposed [Nout,K] fp32, alpha folded
__device__ float g_wt2[344064];
__device__ float g_wt3[172032];
__device__ float g_wtb[86016];

// ---------------- helpers ----------------
__device__ __forceinline__ uint32_t s2u(const void* p) {
    uint32_t a;
    asm("{ .reg .u64 t; cvta.to.shared.u64 t, %1; cvt.u32.u64 %0, t; }"
        : "=r"(a) : "l"(p));
    return a;
}

__device__ __forceinline__ void cp16(uint32_t dst, const void* src) {
    asm volatile("cp.async.cg.shared.global [%0], [%1], 16;"
                 :: "r"(dst), "l"(src));
}

__device__ __forceinline__ uint32_t f2tf(float x) {
    uint32_t r;
    asm("cvt.rna.tf32.f32 %0, %1;" : "=r"(r) : "f"(x));
    return r;
}

__device__ __forceinline__ void mma_tf32(float* d, const uint32_t* a,
                                         uint32_t b0, uint32_t b1) {
    asm volatile(
        "mma.sync.aligned.m16n8k8.row.col.f32.tf32.tf32.f32 "
        "{%0,%1,%2,%3}, {%4,%5,%6,%7}, {%8,%9}, {%0,%1,%2,%3};"
        : "+f"(d[0]), "+f"(d[1]), "+f"(d[2]), "+f"(d[3])
        : "r"(a[0]), "r"(a[1]), "r"(a[2]), "r"(a[3]), "r"(b0), "r"(b1));
}

// ---------------- 3xTF32 GEMM, two concatenated operand sets ----------------
// C[M, Nout] = A1[M,K1] @ B1[Nout,K1]^T + A2[M,K2] @ B2[Nout,K2]^T
// (fp32 in/out, 3xTF32 hi/lo split products: hh + hl + lh)
// blockIdx.z batches independent blocks with A/C column strides.
// BM=128, BN=128 or 64, BK=16, 256 threads, 3-stage cp.async pipeline.
// act=1: apply f*sigmoid(|f|)/|f| (l=0 NormActivation) elementwise in epilogue.
template <int BN>
__global__ __launch_bounds__(256, 2) void gemm_tf32(
    const float* __restrict__ A1, int lda1, size_t sAz1,
    const float* __restrict__ B1, int ldb1, int nc1,
    const float* __restrict__ A2, int lda2, size_t sAz2,
    const float* __restrict__ B2, int ldb2, int nc2,
    float* __restrict__ C, int ldc, size_t sCz, int act)
{
    constexpr int WN = (BN == 128) ? 4 : 2;   // warps along N
    constexpr int MT = (BN == 128) ? 4 : 2;   // m16-tiles per warp
    constexpr int ST = 3;
    extern __shared__ float dsm[];
    float* sAb = dsm;                   // [ST][128*20]
    float* sBb = dsm + ST * 128 * 20;   // [ST][BN*20]

    A1 += (size_t)blockIdx.z * sAz1;
    A2 += (size_t)blockIdx.z * sAz2;
    C  += (size_t)blockIdx.z * sCz;

    const int tid = threadIdx.x, wid = tid >> 5, lane = tid & 31;
    const int g = lane >> 2, t = lane & 3;
    const int wm = wid / WN, wn = wid % WN;
    const int row0 = blockIdx.y << 7;
    const int n0   = blockIdx.x * BN;
    const int tot  = nc1 + nc2;

    float acc[MT][4][4] = {};

    auto issue = [&](int cc, int s) {
        if (cc < tot) {
            const float* Asrc; const float* Bsrc; int la, lb;
            if (cc < nc1) {
                Asrc = A1 + (size_t)row0 * lda1 + cc * 16;
                Bsrc = B1 + (size_t)n0 * ldb1 + cc * 16;
                la = lda1; lb = ldb1;
            } else {
                int c2 = cc - nc1;
                Asrc = A2 + (size_t)row0 * lda2 + c2 * 16;
                Bsrc = B2 + (size_t)n0 * ldb2 + c2 * 16;
                la = lda2; lb = ldb2;
            }
            uint32_t da = s2u(sAb + s * (128 * 20));
            #pragma unroll
            for (int i = tid; i < 512; i += 256) {
                int r = i >> 2, u = i & 3;
                cp16(da + r * 80 + u * 16, Asrc + (size_t)r * la + u * 4);
            }
            uint32_t db = s2u(sBb + s * (BN * 20));
            #pragma unroll
            for (int i = tid; i < BN * 4; i += 256) {
                int r = i >> 2, u = i & 3;
                cp16(db + r * 80 + u * 16, Bsrc + (size_t)r * lb + u * 4);
            }
        }
        asm volatile("cp.async.commit_group;");
    };

    issue(0, 0); issue(1, 1); issue(2, 2);

    for (int cc = 0; cc < tot; cc++) {
        asm volatile("cp.async.wait_group 2;");
        __syncthreads();

        const int s = cc % ST;
        const float* a = sAb + s * (128 * 20);
        const float* b = sBb + s * (BN * 20);

        #pragma unroll
        for (int ks = 0; ks < 2; ks++) {
            const int kb = ks * 8;
            uint32_t bhi[4][2], blo[4][2];
            #pragma unroll
            for (int nt = 0; nt < 4; nt++) {
                int nr = wn * 32 + nt * 8 + g;
                float f0 = b[nr * 20 + kb + t];
                float f1 = b[nr * 20 + kb + 4 + t];
                bhi[nt][0] = f2tf(f0);
                blo[nt][0] = f2tf(f0 - __uint_as_float(bhi[nt][0]));
                bhi[nt][1] = f2tf(f1);
                blo[nt][1] = f2tf(f1 - __uint_as_float(bhi[nt][1]));
            }
            #pragma unroll
            for (int mt = 0; mt < MT; mt++) {
                int r0 = wm * (MT * 16) + mt * 16 + g;
                float a0 = a[r0 * 20 + kb + t];
                float a1 = a[(r0 + 8) * 20 + kb + t];
                float a2 = a[r0 * 20 + kb + 4 + t];
                float a3 = a[(r0 + 8) * 20 + kb + 4 + t];
                uint32_t ahi[4], alo[4];
                ahi[0] = f2tf(a0); alo[0] = f2tf(a0 - __uint_as_float(ahi[0]));
                ahi[1] = f2tf(a1); alo[1] = f2tf(a1 - __uint_as_float(ahi[1]));
                ahi[2] = f2tf(a2); alo[2] = f2tf(a2 - __uint_as_float(ahi[2]));
                ahi[3] = f2tf(a3); alo[3] = f2tf(a3 - __uint_as_float(ahi[3]));
                #pragma unroll
                for (int nt = 0; nt < 4; nt++) {
                    mma_tf32(acc[mt][nt], ahi, bhi[nt][0], bhi[nt][1]);
                    mma_tf32(acc[mt][nt], ahi, blo[nt][0], blo[nt][1]);
                    mma_tf32(acc[mt][nt], alo, bhi[nt][0], bhi[nt][1]);
                }
            }
        }
        __syncthreads();
        issue(cc + 3, s);
    }

    // epilogue
    const int tig = lane & 3;
    #pragma unroll
    for (int mt = 0; mt < MT; mt++) {
        int r = row0 + wm * (MT * 16) + mt * 16 + g;
        #pragma unroll
        for (int nt = 0; nt < 4; nt++) {
            int cI = n0 + wn * 32 + nt * 8 + tig * 2;
            float v[4] = {acc[mt][nt][0], acc[mt][nt][1],
                          acc[mt][nt][2], acc[mt][nt][3]};
            if (act) {
                #pragma unroll
                for (int q = 0; q < 4; q++) {
                    float nn = sqrtf(v[q] * v[q] + 1e-8f);
                    float sg = 1.0f / (1.0f + expf(-nn));
                    v[q] = v[q] * sg / nn;
                }
            }
            float* p0 = C + (size_t)r * ldc + cI;
            float* p1 = p0 + (size_t)8 * ldc;
            *(float2*)p0 = make_float2(v[0], v[1]);
            *(float2*)p1 = make_float2(v[2], v[3]);
        }
    }
}

// ---------------- fused weight prep: all 12 segments in one launch ----------
// fp32 [K,Nout] -> fp32 [Nout,K], alpha=1/sqrt(K) folded
__global__ void conv_w_all(const float* __restrict__ w1, const float* __restrict__ w2,
                           const float* __restrict__ w3, const float* __restrict__ wb,
                           float* __restrict__ t1, float* __restrict__ t2,
                           float* __restrict__ t3, float* __restrict__ tb) {
    int idx = blockIdx.x * 256 + threadIdx.x;
    if (idx >= 774144) return;
    const int ends[12] = {131072, 163840, 172032, 434176, 499712, 516096,
                          647168, 679936, 688128, 753664, 770048, 774144};
    const int Ks[12]   = {256, 128, 64, 512, 256, 128, 512, 256, 128, 256, 128, 64};
    const int Ns[12]   = {512, 256, 128, 512, 256, 128, 256, 128, 64, 256, 128, 64};
    int sidx = 0;
    while (idx >= ends[sidx]) sidx++;
    int start = sidx ? ends[sidx - 1] : 0;
    const float* src; float* dst; int tbase;
    if (sidx < 3)      { src = w1; dst = t1; tbase = 0; }
    else if (sidx < 6) { src = w2; dst = t2; tbase = 172032; }
    else if (sidx < 9) { src = w3; dst = t3; tbase = 516096; }
    else               { src = wb; dst = tb; tbase = 688128; }
    int segoff = start - tbase;
    int local  = idx - start;
    int K = Ks[sidx], Nout = Ns[sidx];
    int u = local / Nout, v = local - u * Nout;
    float alpha = 1.0f / sqrtf((float)K);
    dst[segoff + (size_t)v * K + u] = src[segoff + local] * alpha;
}

// ---------------- x interleaved -> planar fp32 ----------------
__global__ void to_planar_kernel(const float* __restrict__ x) {
    int idx = blockIdx.x * 256 + threadIdx.x;
    if (idx >= NROWS * DIN) return;
    int n = idx / DIN, j = idx - n * DIN;
    int src;
    if (j < 256) {
        src = j;
    } else if (j < 640) {
        int p = j - 256;
        src = 256 + (p & 127) * 3 + (p >> 7);
    } else {
        int p = j - 640;
        src = 640 + (p & 63) * 5 + (p >> 6);
    }
    g_xp[idx] = x[(size_t)n * DIN + src];
}

// ---------------- NormActivation l>0 (in place, planar fp32) ----------------
template <int L>
__global__ void normact_kernel(float* __restrict__ H, int o, int m) {
    int idx = blockIdx.x * 256 + threadIdx.x;
    if (idx >= NROWS * m) return;
    int n = idx / m, v = idx - n * m;
    float* p = H + (size_t)n * DH + o + v;
    float f[L];
    float s2 = 1e-8f;
    #pragma unroll
    for (int i = 0; i < L; i++) { f[i] = p[(size_t)i * m]; s2 += f[i] * f[i]; }
    float nn = sqrtf(s2);
    float sg = 1.0f / (1.0f + expf(-nn));
    float sc = sg / nn;
    #pragma unroll
    for (int i = 0; i < L; i++) p[(size_t)i * m] = f[i] * sc;
}

// ---------------- BatchNorm ----------------
__global__ void bn_zero_kernel() {
    int t = threadIdx.x;
    if (t < 256) g_sum0[t] = 0.0f;
    if (t < 448) g_ssq[t]  = 0.0f;
}

__global__ void bn_reduce_kernel() {
    const int tid = threadIdx.x;
    const int r0  = blockIdx.x * 128;     // 256 blocks * 128 rows
    float s[4] = {0, 0, 0, 0}, q[4] = {0, 0, 0, 0};
    for (int r = 0; r < 128; r++) {
        const float* row = g_outp + (size_t)(r0 + r) * DIN;
        #pragma unroll
        for (int k = 0; k < 4; k++) {
            int j = tid + (k << 8);
            if (j < DIN) {
                float v = row[j];
                s[k] += v;
                q[k] += v * v;
            }
        }
    }
    #pragma unroll
    for (int k = 0; k < 4; k++) {
        int j = tid + (k << 8);
        if (j >= DIN) continue;
        if (j < 256) {
            atomicAdd(&g_sum0[j], s[k]);
            atomicAdd(&g_ssq[j], q[k]);
        } else if (j < 640) {
            atomicAdd(&g_ssq[256 + ((j - 256) & 127)], q[k]);
        } else {
            atomicAdd(&g_ssq[384 + ((j - 640) & 63)], q[k]);
        }
    }
}

__global__ void bn_apply_kernel(const float* __restrict__ bnw,
                                const float* __restrict__ bnb,
                                float* __restrict__ out) {
    int idx = blockIdx.x * 256 + threadIdx.x;
    if (idx >= NROWS * DIN) return;
    int n = idx / DIN, jo = idx - n * DIN;
    const float invN = 1.0f / (float)NROWS;
    float g;
    if (jo < 256) {
        float f   = g_outp[(size_t)n * DIN + jo];
        float mu  = g_sum0[jo] * invN;
        float var = g_ssq[jo] * invN - mu * mu;
        g = (f - mu) * bnw[jo] * rsqrtf(var + 1e-5f) + bnb[jo];
    } else if (jo < 640) {
        int p = jo - 256, v = p / 3, i = p - v * 3;
        float f  = g_outp[(size_t)n * DIN + 256 + (i << 7) + v];
        float n2 = g_ssq[256 + v] * (invN * (1.0f / 3.0f));
        g = f * bnw[256 + v] * rsqrtf(n2 + 1e-5f);
    } else {
        int p = jo - 640, v = p / 5, i = p - v * 5;
        float f  = g_outp[(size_t)n * DIN + 640 + (i << 6) + v];
        float n2 = g_ssq[384 + v] * (invN * (1.0f / 5.0f));
        g = f * bnw[384 + v] * rsqrtf(n2 + 1e-5f);
    }
    out[idx] = g;
}

// ---------------- launch ----------------
#define SMEM128 (3 * (128 * 20 + 128 * 20) * 4)   // 61440
#define SMEM64  (3 * (128 * 20 + 64 * 20) * 4)    // 46080

extern "C" void kernel_launch(void* const* d_in, const int* in_sizes, int n_in,
                              void* d_out, int out_size) {
    const float* x   = (const float*)d_in[0];
    const float* w1  = (const float*)d_in[1];
    const float* w2  = (const float*)d_in[2];
    const float* w3  = (const float*)d_in[3];
    const float* wb  = (const float*)d_in[4];
    const float* bnw = (const float*)d_in[5];
    const float* bnb = (const float*)d_in[6];
    float* out = (float*)d_out;

    cudaFuncSetAttribute(gemm_tf32<128>, cudaFuncAttributeMaxDynamicSharedMemorySize, SMEM128);
    cudaFuncSetAttribute(gemm_tf32<64>,  cudaFuncAttributeMaxDynamicSharedMemorySize, SMEM64);

    float *xp, *h1, *h2, *op, *wt1, *wt2, *wt3, *wtb;
    cudaGetSymbolAddress((void**)&xp,  g_xp);
    cudaGetSymbolAddress((void**)&h1,  g_h1);
    cudaGetSymbolAddress((void**)&h2,  g_h2);
    cudaGetSymbolAddress((void**)&op,  g_outp);
    cudaGetSymbolAddress((void**)&wt1, g_wt1);
    cudaGetSymbolAddress((void**)&wt2, g_wt2);
    cudaGetSymbolAddress((void**)&wt3, g_wt3);
    cudaGetSymbolAddress((void**)&wtb, g_wtb);

    conv_w_all<<<3024, 256>>>(w1, w2, w3, wb, wt1, wt2, wt3, wtb);
    to_planar_kernel<<<(NROWS * DIN) / 256, 256>>>(x);

    // single-operand-set gemm
    auto gemm = [&](const float* A, int lda, size_t sAz, const float* B,
                    float* Cp, int ldc, size_t sCz,
                    int K, int Nout, int nz, int act) {
        if (Nout >= 128) {
            dim3 grid(Nout / 128, NROWS / 128, nz);
            gemm_tf32<128><<<grid, 256, SMEM128>>>(
                A, lda, sAz, B, K, K / 16,
                A, lda, sAz, B, K, 0,
                Cp, ldc, sCz, act);
        } else {
            dim3 grid(Nout / 64, NROWS / 128, nz);
            gemm_tf32<64><<<grid, 256, SMEM64>>>(
                A, lda, sAz, B, K, K / 16,
                A, lda, sAz, B, K, 0,
                Cp, ldc, sCz, act);
        }
    };
    // fused two-operand-set gemm (linear3 + skip)
    auto gemm2 = [&](const float* A1p, int lda1, size_t sAz1, const float* B1, int K1,
                     const float* A2p, int lda2, size_t sAz2, const float* B2, int K2,
                     float* Cp, int ldc, size_t sCz, int Nout, int nz) {
        if (Nout >= 128) {
            dim3 grid(Nout / 128, NROWS / 128, nz);
            gemm_tf32<128><<<grid, 256, SMEM128>>>(
                A1p, lda1, sAz1, B1, K1, K1 / 16,
                A2p, lda2, sAz2, B2, K2, K2 / 16,
                Cp, ldc, sCz, 0);
        } else {
            dim3 grid(Nout / 64, NROWS / 128, nz);
            gemm_tf32<64><<<grid, 256, SMEM64>>>(
                A1p, lda1, sAz1, B1, K1, K1 / 16,
                A2p, lda2, sAz2, B2, K2, K2 / 16,
                Cp, ldc, sCz, 0);
        }
    };

    // layer 1: xp -> h1   (l0 gemm fuses scalar NormActivation)
    gemm(xp,        DIN, 0,   wt1,          h1,        DH, 0,   256, 512, 1, 1);
    gemm(xp + 256,  DIN, 128, wt1 + 131072, h1 + 512,  DH, 256, 128, 256, 3, 0);
    gemm(xp + 640,  DIN, 64,  wt1 + 163840, h1 + 1280, DH, 128,  64, 128, 5, 0);

    normact_kernel<3><<<(NROWS * 256) / 256, 256>>>(h1, 512, 256);
    normact_kernel<5><<<(NROWS * 128) / 256, 256>>>(h1, 1280, 128);

    // layer 2: h1 -> h2   (l0 gemm fuses scalar NormActivation)
    gemm(h1,        DH, 0,    wt2,          h2,        DH, 0,   512, 512, 1, 1);
    gemm(h1 + 512,  DH, 256,  wt2 + 262144, h2 + 512,  DH, 256, 256, 256, 3, 0);
    gemm(h1 + 1280, DH, 128,  wt2 + 327680, h2 + 1280, DH, 128, 128, 128, 5, 0);

    normact_kernel<3><<<(NROWS * 256) / 256, 256>>>(h2, 512, 256);
    normact_kernel<5><<<(NROWS * 128) / 256, 256>>>(h2, 1280, 128);

    // layer 3 + skip, fused concat-K: op = h2@W3 + xp@Wb
    gemm2(h2,        DH, 0,   wt3,          512, xp,       DIN, 0,   wtb,         256,
          op,       DIN, 0,   256, 1);
    gemm2(h2 + 512,  DH, 256, wt3 + 131072, 256, xp + 256, DIN, 128, wtb + 65536, 128,
          op + 256, DIN, 128, 128, 3);
    gemm2(h2 + 1280, DH, 128, wt3 + 163840, 128, xp + 640, DIN, 64,  wtb + 81920,  64,
          op + 640, DIN, 64,   64, 5);

    // batch norm -> interleaved fp32 output
    bn_zero_kernel<<<1, 512>>>();
    bn_reduce_kernel<<<256, 256>>>();
    bn_apply_kernel<<<(NROWS * DIN) / 256, 256>>>(bnw, bnb, out);
}